// round 1
// baseline (speedup 1.0000x reference)
#include <cuda_runtime.h>
#include <cstdint>

#define NL 8
#define T_STATIC 524288u   // 2^19
#define T_XY     32768u    // 2^15
#define T_PL     8192u     // 2^13
#define P1 2654435761u
#define P2 805459861u

__device__ float g_scales[NL];
__device__ float g_red_xy[NL * T_XY];
__device__ float g_red_xz[NL * T_PL];
__device__ float g_red_yz[NL * T_PL];

// ---------------------------------------------------------------------------
// Init: per-level scales computed in double to match numpy exp2 semantics.
// ---------------------------------------------------------------------------
__global__ void init_scales_kernel() {
    int l = threadIdx.x;
    if (l < NL) {
        double s = exp2((double)l * (6.0 / 7.0)) * 512.0 - 1.0;
        g_scales[l] = (float)s;
    }
}

// ---------------------------------------------------------------------------
// Fold time-blend + Lagrange basis into a scalar table per (plane,level,entry):
//   red[e] = sum_i coef_i * ((1-w2)*tab[i1][e][i] + w2*tab[i2][e][i])
// which = 0 -> xy, 1 -> xz, 2 -> yz
// ---------------------------------------------------------------------------
__global__ void reduce_kernel(const float4* __restrict__ tab,
                              const float* __restrict__ tptr,
                              int which, int T) {
    int e = blockIdx.x * blockDim.x + threadIdx.x;
    int total = NL * T;
    if (e >= total) return;

    float t = __ldg(tptr);
    float idxf = t * 7.0f;           // t * (TIME_RES - 1)
    float fi1 = floorf(idxf);
    int i1 = (int)fi1;
    int i2 = (int)ceilf(idxf);
    float w2 = idxf - fi1;
    float w1 = 1.0f - w2;

    const float tn0 = 0.0f;
    const float tn1 = (float)(1.0 / 3.0);
    const float tn2 = (float)(2.0 / 3.0);
    const float tn3 = 1.0f;
    float tnv[4] = {tn0, tn1, tn2, tn3};
    float coef[4];
#pragma unroll
    for (int ii = 0; ii < 4; ii++) {
        float c = 1.0f;
#pragma unroll
        for (int m = 0; m < 4; m++) {
            if (m != ii) c = c * (t - tnv[m]) / (tnv[ii] - tnv[m]);
        }
        coef[ii] = c;
    }

    float4 v1 = __ldg(tab + (size_t)i1 * total + e);
    float4 v2 = __ldg(tab + (size_t)i2 * total + e);
    float r = coef[0] * (w1 * v1.x + w2 * v2.x)
            + coef[1] * (w1 * v1.y + w2 * v2.y)
            + coef[2] * (w1 * v1.z + w2 * v2.z)
            + coef[3] * (w1 * v1.w + w2 * v2.w);

    if (which == 0)      g_red_xy[e] = r;
    else if (which == 1) g_red_xz[e] = r;
    else                 g_red_yz[e] = r;
}

// ---------------------------------------------------------------------------
// Dynamic 2D plane lookup against a reduced scalar table (8 levels).
// ---------------------------------------------------------------------------
__device__ __forceinline__ void dyn_plane(float a, float b,
                                          const float* __restrict__ red,
                                          uint32_t mask,
                                          const float* __restrict__ sc,
                                          float* out8) {
#pragma unroll
    for (int l = 0; l < NL; l++) {
        float s = sc[l];
        float pa = __fadd_rn(__fmul_rn(a, s), 0.5f);
        float pb = __fadd_rn(__fmul_rn(b, s), 0.5f);
        float ba = floorf(pa), bb = floorf(pb);
        float fa = pa - ba, fb = pb - bb;
        uint32_t ua = (uint32_t)ba, ub = (uint32_t)bb;
        uint32_t ha0 = ua,             ha1 = ua + 1u;
        uint32_t hb0 = ub * P1,        hb1 = hb0 + P1;
        float ga = 1.0f - fa, gb = 1.0f - fb;
        const float* r = red + (size_t)l * (mask + 1u);

        float acc;
        acc  = (ga * gb) * __ldg(r + ((ha0 ^ hb0) & mask));
        acc += (fa * gb) * __ldg(r + ((ha1 ^ hb0) & mask));
        acc += (ga * fb) * __ldg(r + ((ha0 ^ hb1) & mask));
        acc += (fa * fb) * __ldg(r + ((ha1 ^ hb1) & mask));
        out8[l] = acc;
    }
}

// ---------------------------------------------------------------------------
// Main: one thread per point. Static 3D trilinear hash-grid (8 levels) +
// 3 dynamic 2D planes against reduced tables.
// ---------------------------------------------------------------------------
__global__ void __launch_bounds__(256)
main_kernel(const float* __restrict__ x,
            const float4* __restrict__ tstat,
            float* __restrict__ out_s,
            float* __restrict__ out_d,
            int N) {
    int i = blockIdx.x * blockDim.x + threadIdx.x;
    if (i >= N) return;

    float x0 = __ldg(x + 3 * (size_t)i + 0);
    float x1 = __ldg(x + 3 * (size_t)i + 1);
    float x2 = __ldg(x + 3 * (size_t)i + 2);

    float sc[NL];
#pragma unroll
    for (int l = 0; l < NL; l++) sc[l] = g_scales[l];

    // ---- static 3D grid ----
#pragma unroll
    for (int l = 0; l < NL; l++) {
        float s = sc[l];
        float px = __fadd_rn(__fmul_rn(x0, s), 0.5f);
        float py = __fadd_rn(__fmul_rn(x1, s), 0.5f);
        float pz = __fadd_rn(__fmul_rn(x2, s), 0.5f);
        float bx = floorf(px), by = floorf(py), bz = floorf(pz);
        float fx = px - bx, fy = py - by, fz = pz - bz;
        uint32_t ux = (uint32_t)bx, uy = (uint32_t)by, uz = (uint32_t)bz;
        uint32_t hx0 = ux,       hx1 = ux + 1u;
        uint32_t hy0 = uy * P1,  hy1 = hy0 + P1;
        uint32_t hz0 = uz * P2,  hz1 = hz0 + P2;
        float gx = 1.0f - fx, gy = 1.0f - fy, gz = 1.0f - fz;
        const float4* tl = tstat + (size_t)l * T_STATIC;

        float a0 = 0.f, a1 = 0.f, a2 = 0.f, a3 = 0.f;
#pragma unroll
        for (int c = 0; c < 8; c++) {
            uint32_t h = ((c & 1) ? hx1 : hx0)
                       ^ ((c & 2) ? hy1 : hy0)
                       ^ ((c & 4) ? hz1 : hz0);
            float w = (((c & 1) ? fx : gx) * ((c & 2) ? fy : gy))
                    * ((c & 4) ? fz : gz);
            float4 v = __ldg(tl + (h & (T_STATIC - 1u)));
            a0 += w * v.x; a1 += w * v.y; a2 += w * v.z; a3 += w * v.w;
        }
        *(float4*)(out_s + (size_t)i * 32 + l * 4) = make_float4(a0, a1, a2, a3);
    }

    // ---- dynamic planes (reduced tables: 1 scalar per entry) ----
    float d8[NL];
    float* od = out_d + (size_t)i * 24;

    dyn_plane(x0, x1, g_red_xy, T_XY - 1u, sc, d8);
    *(float4*)(od + 0) = make_float4(d8[0], d8[1], d8[2], d8[3]);
    *(float4*)(od + 4) = make_float4(d8[4], d8[5], d8[6], d8[7]);

    dyn_plane(x0, x2, g_red_xz, T_PL - 1u, sc, d8);
    *(float4*)(od + 8)  = make_float4(d8[0], d8[1], d8[2], d8[3]);
    *(float4*)(od + 12) = make_float4(d8[4], d8[5], d8[6], d8[7]);

    dyn_plane(x1, x2, g_red_yz, T_PL - 1u, sc, d8);
    *(float4*)(od + 16) = make_float4(d8[0], d8[1], d8[2], d8[3]);
    *(float4*)(od + 20) = make_float4(d8[4], d8[5], d8[6], d8[7]);
}

// ---------------------------------------------------------------------------
extern "C" void kernel_launch(void* const* d_in, const int* in_sizes, int n_in,
                              void* d_out, int out_size) {
    const float* x     = (const float*)d_in[0];
    const float* tptr  = (const float*)d_in[1];
    const float* tstat = (const float*)d_in[2];
    const float* txy   = (const float*)d_in[3];
    const float* txz   = (const float*)d_in[4];
    const float* tyz   = (const float*)d_in[5];

    int N = in_sizes[0] / 3;
    float* out_s = (float*)d_out;
    float* out_d = (float*)d_out + (size_t)N * 32;

    init_scales_kernel<<<1, 8>>>();

    {
        int total = NL * (int)T_XY;
        reduce_kernel<<<(total + 255) / 256, 256>>>((const float4*)txy, tptr, 0, (int)T_XY);
    }
    {
        int total = NL * (int)T_PL;
        reduce_kernel<<<(total + 255) / 256, 256>>>((const float4*)txz, tptr, 1, (int)T_PL);
        reduce_kernel<<<(total + 255) / 256, 256>>>((const float4*)tyz, tptr, 2, (int)T_PL);
    }

    main_kernel<<<(N + 255) / 256, 256>>>(x, (const float4*)tstat, out_s, out_d, N);
}